// round 1
// baseline (speedup 1.0000x reference)
#include <cuda_runtime.h>
#include <cuda_bf16.h>
#include <math.h>

#define B_    8
#define S_    2048
#define HID_  1024
#define NH_   16
#define HD_   64
#define SP_   1024      // pooled q length (S_/2)
#define NQKV_ 3072

// ---------------- scratch (device globals: no allocations allowed) ----------
__device__ float g_q [B_*S_*HID_];        // 64 MB  q pre-pool, [B,S,HID]
__device__ float g_k [B_*NH_*S_*HD_];     // 64 MB  k head-major [B,NH,S,HD]
__device__ float g_v [B_*NH_*S_*HD_];     // 64 MB  v head-major [B,NH,S,HD]
__device__ float g_qh[B_*NH_*SP_*HD_];    // 32 MB  pooled+rope q [B,NH,SP,HD]
__device__ int   g_len[B_];

// ---------------- kernel 1: per-batch prefix lengths (dtype-sniffing) -------
__global__ void len_kernel(const void* __restrict__ mask) {
    __shared__ int sred[256];
    const int* mi = (const int*)mask;
    // Element 16 of batch 0 is guaranteed true (lengths >= 1024).
    // int32 layout  -> word = 1
    // float32 layout-> word = 0x3F800000
    // uint8 (bool_) -> word at byte 64 = 0x01010101
    int w = mi[16];
    int mode = (w == 1) ? 0 : ((w == 0x3F800000) ? 1 : 2);
    for (int b = 0; b < B_; b++) {
        int cnt = 0;
        for (int s = threadIdx.x; s < S_; s += 256) {
            int v;
            if (mode == 0)      v = (mi[b*S_+s] != 0);
            else if (mode == 1) v = (((const float*)mask)[b*S_+s] != 0.0f);
            else                v = (((const unsigned char*)mask)[b*S_+s] != 0);
            cnt += v;
        }
        sred[threadIdx.x] = cnt;
        __syncthreads();
        for (int st = 128; st > 0; st >>= 1) {
            if (threadIdx.x < st) sred[threadIdx.x] += sred[threadIdx.x + st];
            __syncthreads();
        }
        if (threadIdx.x == 0) g_len[b] = sred[0];
        __syncthreads();
    }
}

// ---------------- kernel 2: QKV GEMM (+bias) with layout scatter ------------
// C[m,n] = sum_k hidden[m,k] * Wqkv[n,k] + b[n];  M=16384, N=3072, K=1024
__global__ __launch_bounds__(256) void qkv_gemm_kernel(
        const float* __restrict__ A, const float* __restrict__ W,
        const float* __restrict__ bias) {
    __shared__ float As[8][132];
    __shared__ float Bs[8][132];
    const int bm = blockIdx.y, bn = blockIdx.x;
    const int tid = threadIdx.x;
    const int tr = tid >> 4, tc = tid & 15;
    const int lr = tid >> 1;          // 0..127
    const int lc = (tid & 1) * 4;     // 0 or 4
    const float* Ab = A + (size_t)bm * 128 * HID_;
    const float* Wb = W + (size_t)bn * 128 * HID_;

    float acc[8][8];
#pragma unroll
    for (int i = 0; i < 8; i++)
#pragma unroll
        for (int j = 0; j < 8; j++) acc[i][j] = 0.0f;

    float4 pa = *(const float4*)(Ab + lr*HID_ + lc);
    float4 pb = *(const float4*)(Wb + lr*HID_ + lc);

    for (int kt = 0; kt < HID_/8; kt++) {
        As[lc+0][lr]=pa.x; As[lc+1][lr]=pa.y; As[lc+2][lr]=pa.z; As[lc+3][lr]=pa.w;
        Bs[lc+0][lr]=pb.x; Bs[lc+1][lr]=pb.y; Bs[lc+2][lr]=pb.z; Bs[lc+3][lr]=pb.w;
        __syncthreads();
        if (kt + 1 < HID_/8) {
            pa = *(const float4*)(Ab + lr*HID_ + (kt+1)*8 + lc);
            pb = *(const float4*)(Wb + lr*HID_ + (kt+1)*8 + lc);
        }
#pragma unroll
        for (int k = 0; k < 8; k++) {
            float am[8], bw[8];
            *(float4*)&am[0] = *(const float4*)&As[k][tr*8];
            *(float4*)&am[4] = *(const float4*)&As[k][tr*8+4];
            *(float4*)&bw[0] = *(const float4*)&Bs[k][tc*8];
            *(float4*)&bw[4] = *(const float4*)&Bs[k][tc*8+4];
#pragma unroll
            for (int i = 0; i < 8; i++)
#pragma unroll
                for (int j = 0; j < 8; j++)
                    acc[i][j] += am[i] * bw[j];
        }
        __syncthreads();
    }

    const int mbase = bm*128 + tr*8;
    const int nbase = bn*128 + tc*8;
#pragma unroll
    for (int i = 0; i < 8; i++) {
        int m = mbase + i;
        int bb = m >> 11;          // /2048
        int s  = m & 2047;
#pragma unroll
        for (int j = 0; j < 8; j++) {
            int n = nbase + j;
            float v = acc[i][j] + bias[n];
            if (n < 1024) {
                g_q[((size_t)(bb*S_+s))*HID_ + n] = v;
            } else if (n < 2048) {
                int nn = n - 1024, hh = nn >> 6, dd = nn & 63;
                g_k[(((size_t)(bb*NH_+hh))*S_ + s)*HD_ + dd] = v;
            } else {
                int nn = n - 2048, hh = nn >> 6, dd = nn & 63;
                g_v[(((size_t)(bb*NH_+hh))*S_ + s)*HD_ + dd] = v;
            }
        }
    }
}

// ---------------- kernel 3: RoPE on K (in place) ----------------------------
__global__ void rope_k_kernel() {
    int idx = blockIdx.x * blockDim.x + threadIdx.x;   // B*NH*S*32 threads exactly
    int i  = idx & 31;
    int s  = (idx >> 5) & (S_ - 1);
    int bh = idx >> 16;                                 // 32*2048 = 65536
    float theta = __expf(-(float)i * (9.210340371976184f / 32.0f)); // 10000^(-i/32)
    float ang = (float)s * theta;
    float sn, cs;
    sincosf(ang, &sn, &cs);
    float2* p = (float2*)(g_k + ((size_t)bh*S_ + s)*HD_) + i;
    float2 x = *p;
    float2 o;
    o.x = x.x*cs - x.y*sn;
    o.y = x.y*cs + x.x*sn;
    *p = o;
}

// ---------------- kernel 4: masked avg-pool q + RoPE at pooled positions ----
__global__ void pool_rope_q_kernel() {
    int idx = blockIdx.x * blockDim.x + threadIdx.x;   // B*NH*SP*32 threads
    int i  = idx & 31;
    int p  = (idx >> 5) & (SP_ - 1);
    int bh = idx >> 15;                                 // 32*1024 = 32768
    int b = bh >> 4, h = bh & 15;
    int len = g_len[b];
    int s0 = 2 * p;
    int c0 = (s0 < len), c1 = (s0 + 1 < len);
    float norm = (c0 + c1 > 0) ? (float)(c0 + c1) : 1.0f;
    const float2* q0 = (const float2*)(g_q + ((size_t)(b*S_+s0  ))*HID_ + h*HD_) + i;
    const float2* q1 = (const float2*)(g_q + ((size_t)(b*S_+s0+1))*HID_ + h*HD_) + i;
    float2 a = c0 ? *q0 : make_float2(0.f, 0.f);
    float2 c = c1 ? *q1 : make_float2(0.f, 0.f);
    float x0 = (a.x + c.x) / norm;
    float x1 = (a.y + c.y) / norm;
    float theta = __expf(-(float)i * (9.210340371976184f / 32.0f));
    float ang = (float)p * theta;
    float sn, cs;
    sincosf(ang, &sn, &cs);
    float2 o;
    o.x = x0*cs - x1*sn;
    o.y = x1*cs + x0*sn;
    ((float2*)(g_qh + ((size_t)bh*SP_ + p)*HD_))[i] = o;
}

// ---------------- kernel 5: flash attention (fp32 SIMT, 128x128 tiles) ------
// grid: (SP_/128, NH, B), block: 256 threads (16x16), per-thread 8q x 8k scores
#define QPITCH 68
#define PPITCH 132
__global__ __launch_bounds__(256, 1) void attn_kernel(float* __restrict__ out) {
    extern __shared__ float smf[];
    float* Qs = smf;                    // [128][68]
    float* Ks = smf + 128*QPITCH;       // [128][68]
    float* Vs = smf + 2*128*QPITCH;     // [128][68]
    float* Ps = smf + 3*128*QPITCH;     // [128][132]
    const int qt = blockIdx.x, h = blockIdx.y, b = blockIdx.z;
    const int len = g_len[b];
    const int tid = threadIdx.x;
    const int tr = tid >> 4, tc = tid & 15;

    // load Q tile, pre-scaled by 1/sqrt(HD)=0.125
    const float* Qg = g_qh + ((size_t)(b*NH_+h)*SP_ + qt*128)*HD_;
    for (int t = tid; t < 128*16; t += 256) {
        int r = t >> 4, c4 = t & 15;
        float4 v = ((const float4*)(Qg + r*HD_))[c4];
        v.x *= 0.125f; v.y *= 0.125f; v.z *= 0.125f; v.w *= 0.125f;
        *(float4*)&Qs[r*QPITCH + c4*4] = v;
    }
    float m[8], l[8], O[8][4];
#pragma unroll
    for (int i = 0; i < 8; i++) {
        m[i] = -1e30f; l[i] = 0.0f;
#pragma unroll
        for (int j = 0; j < 4; j++) O[i][j] = 0.0f;
    }
    __syncthreads();

    const float* Kg = g_k + (size_t)(b*NH_+h)*S_*HD_;
    const float* Vg = g_v + (size_t)(b*NH_+h)*S_*HD_;
    const int ntiles = (len + 127) >> 7;   // prefix mask -> skip fully-masked tiles

    for (int kt = 0; kt < ntiles; kt++) {
        for (int t = tid; t < 128*16; t += 256) {
            int r = t >> 4, c4 = t & 15;
            *(float4*)&Ks[r*QPITCH + c4*4] = ((const float4*)(Kg + (size_t)(kt*128+r)*HD_))[c4];
            *(float4*)&Vs[r*QPITCH + c4*4] = ((const float4*)(Vg + (size_t)(kt*128+r)*HD_))[c4];
        }
        __syncthreads();

        // ---- scores: s[8][8] over d (dot-product form, float4 LDS) ----
        float s[8][8];
#pragma unroll
        for (int i = 0; i < 8; i++)
#pragma unroll
            for (int j = 0; j < 8; j++) s[i][j] = 0.0f;

#pragma unroll
        for (int d4 = 0; d4 < 16; d4++) {
            float4 kr[4];
#pragma unroll
            for (int j = 0; j < 4; j++) kr[j] = *(const float4*)&Ks[(tc*8+j)*QPITCH + d4*4];
#pragma unroll
            for (int i = 0; i < 8; i++) {
                float4 qv = *(const float4*)&Qs[(tr*8+i)*QPITCH + d4*4];
#pragma unroll
                for (int j = 0; j < 4; j++)
                    s[i][j] += qv.x*kr[j].x + qv.y*kr[j].y + qv.z*kr[j].z + qv.w*kr[j].w;
            }
#pragma unroll
            for (int j = 0; j < 4; j++) kr[j] = *(const float4*)&Ks[(tc*8+4+j)*QPITCH + d4*4];
#pragma unroll
            for (int i = 0; i < 8; i++) {
                float4 qv = *(const float4*)&Qs[(tr*8+i)*QPITCH + d4*4];
#pragma unroll
                for (int j = 0; j < 4; j++)
                    s[i][4+j] += qv.x*kr[j].x + qv.y*kr[j].y + qv.z*kr[j].z + qv.w*kr[j].w;
            }
        }

        // ---- mask partial tile ----
        const int kbase = kt * 128;
        if (kbase + 128 > len) {
#pragma unroll
            for (int j = 0; j < 8; j++) {
                if (kbase + tc*8 + j >= len) {
#pragma unroll
                    for (int i = 0; i < 8; i++) s[i][j] = -1e30f;
                }
            }
        }

        // ---- online softmax (row reductions across 16 lanes) ----
#pragma unroll
        for (int i = 0; i < 8; i++) {
            float mx = s[i][0];
#pragma unroll
            for (int j = 1; j < 8; j++) mx = fmaxf(mx, s[i][j]);
            mx = fmaxf(mx, __shfl_xor_sync(0xffffffffu, mx, 1));
            mx = fmaxf(mx, __shfl_xor_sync(0xffffffffu, mx, 2));
            mx = fmaxf(mx, __shfl_xor_sync(0xffffffffu, mx, 4));
            mx = fmaxf(mx, __shfl_xor_sync(0xffffffffu, mx, 8));
            float mnew = fmaxf(m[i], mx);
            float corr = __expf(m[i] - mnew);
            float rs = 0.0f;
#pragma unroll
            for (int j = 0; j < 8; j++) {
                float e = __expf(s[i][j] - mnew);
                s[i][j] = e;
                rs += e;
            }
            rs += __shfl_xor_sync(0xffffffffu, rs, 1);
            rs += __shfl_xor_sync(0xffffffffu, rs, 2);
            rs += __shfl_xor_sync(0xffffffffu, rs, 4);
            rs += __shfl_xor_sync(0xffffffffu, rs, 8);
            l[i] = l[i]*corr + rs;
            m[i] = mnew;
#pragma unroll
            for (int j = 0; j < 4; j++) O[i][j] *= corr;
            float4 p0 = make_float4(s[i][0], s[i][1], s[i][2], s[i][3]);
            float4 p1 = make_float4(s[i][4], s[i][5], s[i][6], s[i][7]);
            *(float4*)&Ps[(tr*8+i)*PPITCH + tc*8]     = p0;
            *(float4*)&Ps[(tr*8+i)*PPITCH + tc*8 + 4] = p1;
        }
        __syncthreads();

        // ---- O += P @ V  (per-thread 8q x 4d, loop over k in chunks of 4) ----
#pragma unroll 4
        for (int k4 = 0; k4 < 32; k4++) {
            float4 vv0 = *(const float4*)&Vs[(k4*4+0)*QPITCH + tc*4];
            float4 vv1 = *(const float4*)&Vs[(k4*4+1)*QPITCH + tc*4];
            float4 vv2 = *(const float4*)&Vs[(k4*4+2)*QPITCH + tc*4];
            float4 vv3 = *(const float4*)&Vs[(k4*4+3)*QPITCH + tc*4];
#pragma unroll
            for (int i = 0; i < 8; i++) {
                float4 pv = *(const float4*)&Ps[(tr*8+i)*PPITCH + k4*4];
                O[i][0] += pv.x*vv0.x + pv.y*vv1.x + pv.z*vv2.x + pv.w*vv3.x;
                O[i][1] += pv.x*vv0.y + pv.y*vv1.y + pv.z*vv2.y + pv.w*vv3.y;
                O[i][2] += pv.x*vv0.z + pv.y*vv1.z + pv.z*vv2.z + pv.w*vv3.z;
                O[i][3] += pv.x*vv0.w + pv.y*vv1.w + pv.z*vv2.w + pv.w*vv3.w;
            }
        }
        __syncthreads();
    }

    // ---- epilogue: 1/l, q_mask zeroing, write [B, SP, NH*HD] ----
#pragma unroll
    for (int i = 0; i < 8; i++) {
        int qg = qt*128 + tr*8 + i;
        float inv = (2*qg < len) ? (1.0f / l[i]) : 0.0f;
        float4 o = make_float4(O[i][0]*inv, O[i][1]*inv, O[i][2]*inv, O[i][3]*inv);
        *(float4*)&out[((size_t)(b*SP_ + qg))*(NH_*HD_) + h*HD_ + tc*4] = o;
    }
}

// ---------------- launcher ---------------------------------------------------
extern "C" void kernel_launch(void* const* d_in, const int* in_sizes, int n_in,
                              void* d_out, int out_size) {
    const float* hidden = (const float*)d_in[0];
    const void*  mask   = d_in[1];
    const float* W      = (const float*)d_in[2];
    const float* bias   = (const float*)d_in[3];
    float* out = (float*)d_out;

    len_kernel<<<1, 256>>>(mask);

    dim3 gg(NQKV_/128, (B_*S_)/128);       // (24, 128)
    qkv_gemm_kernel<<<gg, 256>>>(hidden, W, bias);

    rope_k_kernel<<<(B_*NH_*S_*32)/256, 256>>>();
    pool_rope_q_kernel<<<(B_*NH_*SP_*32)/256, 256>>>();

    const int attn_smem = (3*128*QPITCH + 128*PPITCH) * (int)sizeof(float); // 172032 B
    cudaFuncSetAttribute(attn_kernel, cudaFuncAttributeMaxDynamicSharedMemorySize, attn_smem);
    dim3 ga(SP_/128, NH_, B_);             // (8, 16, 8)
    attn_kernel<<<ga, 256, attn_smem>>>(out);
}

// round 3
// speedup vs baseline: 3.4170x; 3.4170x over previous
#include <cuda_runtime.h>
#include <cuda_bf16.h>
#include <math.h>

#define B_    8
#define S_    2048
#define HID_  1024
#define NH_   16
#define HD_   64
#define SP_   1024
#define NQKV_ 3072

// ---------------- scratch ----------------------------------------------------
__device__ float g_q [B_*S_*HID_];        // q pre-pool, [B,S,HID]
__device__ float g_k [B_*NH_*S_*HD_];     // k head-major [B,NH,S,HD] (roped)
__device__ float g_v [B_*NH_*S_*HD_];     // v head-major
__device__ float g_qh[B_*NH_*SP_*HD_];    // pooled+roped q
__device__ int   g_len[B_];

// ---------------- tf32 helpers -----------------------------------------------
__device__ __forceinline__ unsigned f2tf(float x) {
    unsigned r; asm("cvt.rna.tf32.f32 %0, %1;" : "=r"(r) : "f"(x)); return r;
}
__device__ __forceinline__ void mma_tf32(float* d,
        unsigned a0, unsigned a1, unsigned a2, unsigned a3,
        unsigned b0, unsigned b1) {
    asm volatile("mma.sync.aligned.m16n8k8.row.col.f32.tf32.tf32.f32 "
        "{%0,%1,%2,%3},{%4,%5,%6,%7},{%8,%9},{%0,%1,%2,%3};\n"
        : "+f"(d[0]), "+f"(d[1]), "+f"(d[2]), "+f"(d[3])
        : "r"(a0), "r"(a1), "r"(a2), "r"(a3), "r"(b0), "r"(b1));
}

// ---------------- kernel 1: per-batch prefix lengths --------------------------
__global__ void len_kernel(const void* __restrict__ mask) {
    __shared__ int sred[256];
    const int* mi = (const int*)mask;
    int w = mi[16];
    int mode = (w == 1) ? 0 : ((w == 0x3F800000) ? 1 : 2);
    for (int b = 0; b < B_; b++) {
        int cnt = 0;
        for (int s = threadIdx.x; s < S_; s += 256) {
            int v;
            if (mode == 0)      v = (mi[b*S_+s] != 0);
            else if (mode == 1) v = (((const float*)mask)[b*S_+s] != 0.0f);
            else                v = (((const unsigned char*)mask)[b*S_+s] != 0);
            cnt += v;
        }
        sred[threadIdx.x] = cnt;
        __syncthreads();
        for (int st = 128; st > 0; st >>= 1) {
            if (threadIdx.x < st) sred[threadIdx.x] += sred[threadIdx.x + st];
            __syncthreads();
        }
        if (threadIdx.x == 0) g_len[b] = sred[0];
        __syncthreads();
    }
}

// ---------------- kernel 2: QKV GEMM, tf32 tensor cores -----------------------
// C[m,n] = hidden[m,:] . Wqkv[n,:] + bias[n];  M=16384, N=3072, K=1024
// Block 128x128, BK=32, 8 warps in 2x4 grid, warp tile 64x32.
#define APITCH 36   // 36 % 32 == 4 -> frag LDS bank = (4*row + col) % 32, conflict-free
__global__ __launch_bounds__(256) void qkv_gemm_tc(
        const float* __restrict__ A, const float* __restrict__ W,
        const float* __restrict__ bias) {
    __shared__ unsigned As[128*APITCH];
    __shared__ unsigned Bs[128*APITCH];
    const int bm = blockIdx.y, bn = blockIdx.x, tid = threadIdx.x;
    const int warp = tid >> 5, lane = tid & 31;
    const int wm = warp >> 2, wn = warp & 3;
    const int g = lane >> 2, c = lane & 3;
    const float* Ab = A + (size_t)bm * 128 * HID_;
    const float* Wb = W + (size_t)bn * 128 * HID_;
    const int lrow = tid >> 3;         // 0..31
    const int lc4  = (tid & 7) * 4;    // 0,4,...,28

    float acc[4][4][4];
#pragma unroll
    for (int i = 0; i < 4; i++)
#pragma unroll
        for (int j = 0; j < 4; j++)
#pragma unroll
            for (int r = 0; r < 4; r++) acc[i][j][r] = 0.0f;

    float4 pa[4], pb[4];
#pragma unroll
    for (int r4 = 0; r4 < 4; r4++) {
        pa[r4] = *(const float4*)(Ab + (size_t)(lrow + r4*32)*HID_ + lc4);
        pb[r4] = *(const float4*)(Wb + (size_t)(lrow + r4*32)*HID_ + lc4);
    }

    for (int kt = 0; kt < HID_/32; kt++) {
#pragma unroll
        for (int r4 = 0; r4 < 4; r4++) {
            int row = lrow + r4*32;
            *(uint4*)&As[row*APITCH + lc4] =
                make_uint4(f2tf(pa[r4].x), f2tf(pa[r4].y), f2tf(pa[r4].z), f2tf(pa[r4].w));
            *(uint4*)&Bs[row*APITCH + lc4] =
                make_uint4(f2tf(pb[r4].x), f2tf(pb[r4].y), f2tf(pb[r4].z), f2tf(pb[r4].w));
        }
        __syncthreads();
        if (kt + 1 < HID_/32) {
            int kbase = (kt+1)*32 + lc4;
#pragma unroll
            for (int r4 = 0; r4 < 4; r4++) {
                pa[r4] = *(const float4*)(Ab + (size_t)(lrow + r4*32)*HID_ + kbase);
                pb[r4] = *(const float4*)(Wb + (size_t)(lrow + r4*32)*HID_ + kbase);
            }
        }
#pragma unroll
        for (int ks = 0; ks < 4; ks++) {
            const int k0 = ks * 8;
            unsigned a[4][4], bfr[4][2];
#pragma unroll
            for (int i = 0; i < 4; i++) {
                int r = wm*64 + i*16 + g;
                a[i][0] = As[r*APITCH + k0 + c];
                a[i][1] = As[(r+8)*APITCH + k0 + c];
                a[i][2] = As[r*APITCH + k0 + 4 + c];
                a[i][3] = As[(r+8)*APITCH + k0 + 4 + c];
            }
#pragma unroll
            for (int j = 0; j < 4; j++) {
                int n = wn*32 + j*8 + g;
                bfr[j][0] = Bs[n*APITCH + k0 + c];
                bfr[j][1] = Bs[n*APITCH + k0 + 4 + c];
            }
#pragma unroll
            for (int i = 0; i < 4; i++)
#pragma unroll
                for (int j = 0; j < 4; j++)
                    mma_tf32(acc[i][j], a[i][0], a[i][1], a[i][2], a[i][3],
                             bfr[j][0], bfr[j][1]);
        }
        __syncthreads();
    }

    // epilogue: bias + scatter to q / k / v layouts
#pragma unroll
    for (int i = 0; i < 4; i++) {
#pragma unroll
        for (int hh = 0; hh < 2; hh++) {
            int m = bm*128 + wm*64 + i*16 + hh*8 + g;
            int bb = m >> 11;
            int s  = m & 2047;
#pragma unroll
            for (int j = 0; j < 4; j++) {
                int n = bn*128 + wn*32 + j*8 + 2*c;
                float v0 = acc[i][j][hh*2+0] + bias[n];
                float v1 = acc[i][j][hh*2+1] + bias[n+1];
                if (n < 1024) {
                    float* p = &g_q[((size_t)(bb*S_+s))*HID_ + n];
                    p[0] = v0; p[1] = v1;
                } else if (n < 2048) {
                    int nn = n - 1024, hhd = nn >> 6, dd = nn & 63;
                    float* p = &g_k[(((size_t)(bb*NH_+hhd))*S_ + s)*HD_ + dd];
                    p[0] = v0; p[1] = v1;
                } else {
                    int nn = n - 2048, hhd = nn >> 6, dd = nn & 63;
                    float* p = &g_v[(((size_t)(bb*NH_+hhd))*S_ + s)*HD_ + dd];
                    p[0] = v0; p[1] = v1;
                }
            }
        }
    }
}

// ---------------- kernel 3: RoPE on K (in place) ------------------------------
__global__ void rope_k_kernel() {
    int idx = blockIdx.x * blockDim.x + threadIdx.x;
    int i  = idx & 31;
    int s  = (idx >> 5) & (S_ - 1);
    int bh = idx >> 16;
    float theta = __expf(-(float)i * (9.210340371976184f / 32.0f));
    float ang = (float)s * theta;
    float sn, cs;
    sincosf(ang, &sn, &cs);
    float2* p = (float2*)(g_k + ((size_t)bh*S_ + s)*HD_) + i;
    float2 x = *p;
    float2 o;
    o.x = x.x*cs - x.y*sn;
    o.y = x.y*cs + x.x*sn;
    *p = o;
}

// ---------------- kernel 4: masked avg-pool q + RoPE --------------------------
__global__ void pool_rope_q_kernel() {
    int idx = blockIdx.x * blockDim.x + threadIdx.x;
    int i  = idx & 31;
    int p  = (idx >> 5) & (SP_ - 1);
    int bh = idx >> 15;
    int b = bh >> 4, h = bh & 15;
    int len = g_len[b];
    int s0 = 2 * p;
    int c0 = (s0 < len), c1 = (s0 + 1 < len);
    float norm = (c0 + c1 > 0) ? (float)(c0 + c1) : 1.0f;
    const float2* q0 = (const float2*)(g_q + ((size_t)(b*S_+s0  ))*HID_ + h*HD_) + i;
    const float2* q1 = (const float2*)(g_q + ((size_t)(b*S_+s0+1))*HID_ + h*HD_) + i;
    float2 a = c0 ? *q0 : make_float2(0.f, 0.f);
    float2 c = c1 ? *q1 : make_float2(0.f, 0.f);
    float x0 = (a.x + c.x) / norm;
    float x1 = (a.y + c.y) / norm;
    float theta = __expf(-(float)i * (9.210340371976184f / 32.0f));
    float ang = (float)p * theta;
    float sn, cs;
    sincosf(ang, &sn, &cs);
    float2 o;
    o.x = x0*cs - x1*sn;
    o.y = x1*cs + x0*sn;
    ((float2*)(g_qh + ((size_t)bh*SP_ + p)*HD_))[i] = o;
}

// ---------------- kernel 5: flash attention, tf32 tensor cores ----------------
// grid (SP/128, NH, B), 256 thr = 8 warps (2x4).
// QK^T: warp tile 64q x 32k; PV: warp tile 64q x 16d.
#define QP 68    // 68 % 32 == 4
#define VP 72    // 72 % 32 == 8
#define PP 132   // 132 % 32 == 4
__global__ __launch_bounds__(256, 1) void attn_tc(float* __restrict__ out) {
    extern __shared__ unsigned sm[];
    unsigned* Qs = sm;                    // [128][QP]
    unsigned* Ks = Qs + 128*QP;           // [128][QP]
    unsigned* Vs = Ks + 128*QP;           // [128][VP] rows = key, cols = d
    unsigned* Ps = Vs + 128*VP;           // [128][PP]
    float*   red = (float*)(Ps + 128*PP); // [128][4]

    const int qt = blockIdx.x, h = blockIdx.y, b = blockIdx.z;
    const int len = g_len[b];
    const int tid = threadIdx.x, warp = tid >> 5, lane = tid & 31;
    const int wm = warp >> 2, wn = warp & 3;
    const int g = lane >> 2, c = lane & 3;

    // Q tile, pre-scaled by 1/sqrt(64)
    const float* Qg = g_qh + ((size_t)(b*NH_+h)*SP_ + qt*128)*HD_;
    for (int t = tid; t < 128*16; t += 256) {
        int r = t >> 4, c4 = t & 15;
        float4 v = ((const float4*)(Qg + r*HD_))[c4];
        *(uint4*)&Qs[r*QP + c4*4] = make_uint4(
            f2tf(v.x*0.125f), f2tf(v.y*0.125f), f2tf(v.z*0.125f), f2tf(v.w*0.125f));
    }

    float O[4][2][4];
    float m[4][2], l[4][2];
#pragma unroll
    for (int i = 0; i < 4; i++)
#pragma unroll
        for (int hh = 0; hh < 2; hh++) {
            m[i][hh] = -1e30f; l[i][hh] = 0.0f;
            O[i][0][hh*2] = O[i][0][hh*2+1] = 0.0f;
            O[i][1][hh*2] = O[i][1][hh*2+1] = 0.0f;
        }
    __syncthreads();

    const float* Kg = g_k + (size_t)(b*NH_+h)*S_*HD_;
    const float* Vg = g_v + (size_t)(b*NH_+h)*S_*HD_;
    const int ntiles = (len + 127) >> 7;

    for (int kt = 0; kt < ntiles; kt++) {
        for (int t = tid; t < 128*16; t += 256) {
            int r = t >> 4, c4 = t & 15;
            float4 kv = ((const float4*)(Kg + (size_t)(kt*128+r)*HD_))[c4];
            *(uint4*)&Ks[r*QP + c4*4] = make_uint4(f2tf(kv.x), f2tf(kv.y), f2tf(kv.z), f2tf(kv.w));
            float4 vv = ((const float4*)(Vg + (size_t)(kt*128+r)*HD_))[c4];
            *(uint4*)&Vs[r*VP + c4*4] = make_uint4(f2tf(vv.x), f2tf(vv.y), f2tf(vv.z), f2tf(vv.w));
        }
        __syncthreads();

        // ---- S = Q K^T (tf32 mma) ----
        float s[4][4][4];
#pragma unroll
        for (int i = 0; i < 4; i++)
#pragma unroll
            for (int j = 0; j < 4; j++)
#pragma unroll
                for (int r = 0; r < 4; r++) s[i][j][r] = 0.0f;

#pragma unroll
        for (int ks = 0; ks < 8; ks++) {
            const int k0 = ks * 8;
            unsigned a[4][4];
#pragma unroll
            for (int i = 0; i < 4; i++) {
                int r = wm*64 + i*16 + g;
                a[i][0] = Qs[r*QP + k0 + c];
                a[i][1] = Qs[(r+8)*QP + k0 + c];
                a[i][2] = Qs[r*QP + k0 + 4 + c];
                a[i][3] = Qs[(r+8)*QP + k0 + 4 + c];
            }
#pragma unroll
            for (int j = 0; j < 4; j++) {
                int n = wn*32 + j*8 + g;
                unsigned b0 = Ks[n*QP + k0 + c];
                unsigned b1 = Ks[n*QP + k0 + 4 + c];
#pragma unroll
                for (int i = 0; i < 4; i++)
                    mma_tf32(s[i][j], a[i][0], a[i][1], a[i][2], a[i][3], b0, b1);
            }
        }

        // ---- mask partial tile (prefix mask) ----
        if (kt == ntiles - 1 && (len & 127)) {
#pragma unroll
            for (int j = 0; j < 4; j++) {
#pragma unroll
                for (int cc = 0; cc < 2; cc++) {
                    int kcol = kt*128 + wn*32 + j*8 + 2*c + cc;
                    if (kcol >= len) {
#pragma unroll
                        for (int i = 0; i < 4; i++) {
                            s[i][j][cc] = -1e30f;
                            s[i][j][2+cc] = -1e30f;
                        }
                    }
                }
            }
        }

        // ---- row max: quad shuffle + cross-warp via smem ----
        float tmax[4][2];
#pragma unroll
        for (int i = 0; i < 4; i++)
#pragma unroll
            for (int hh = 0; hh < 2; hh++) {
                float mx = s[i][0][hh*2];
                mx = fmaxf(mx, s[i][0][hh*2+1]);
#pragma unroll
                for (int j = 1; j < 4; j++) {
                    mx = fmaxf(mx, s[i][j][hh*2]);
                    mx = fmaxf(mx, s[i][j][hh*2+1]);
                }
                mx = fmaxf(mx, __shfl_xor_sync(0xffffffffu, mx, 1));
                mx = fmaxf(mx, __shfl_xor_sync(0xffffffffu, mx, 2));
                tmax[i][hh] = mx;
            }
        if (c == 0) {
#pragma unroll
            for (int i = 0; i < 4; i++)
#pragma unroll
                for (int hh = 0; hh < 2; hh++)
                    red[(wm*64 + i*16 + hh*8 + g)*4 + wn] = tmax[i][hh];
        }
        __syncthreads();

        // ---- exp, P store, O rescale, partial row sums ----
        float corr[4][2], rs[4][2];
#pragma unroll
        for (int i = 0; i < 4; i++)
#pragma unroll
            for (int hh = 0; hh < 2; hh++) {
                int row = wm*64 + i*16 + hh*8 + g;
                float mx = fmaxf(fmaxf(red[row*4+0], red[row*4+1]),
                                 fmaxf(red[row*4+2], red[row*4+3]));
                float mnew = fmaxf(m[i][hh], mx);
                float cr = __expf(m[i][hh] - mnew);
                corr[i][hh] = cr;
                m[i][hh] = mnew;
                float r = 0.0f;
#pragma unroll
                for (int j = 0; j < 4; j++) {
                    float e0 = __expf(s[i][j][hh*2]   - mnew);
                    float e1 = __expf(s[i][j][hh*2+1] - mnew);
                    r += e0 + e1;
                    *(uint2*)&Ps[row*PP + wn*32 + j*8 + 2*c] =
                        make_uint2(f2tf(e0), f2tf(e1));
                }
                r += __shfl_xor_sync(0xffffffffu, r, 1);
                r += __shfl_xor_sync(0xffffffffu, r, 2);
                rs[i][hh] = r;
                O[i][0][hh*2]   *= cr;  O[i][0][hh*2+1] *= cr;
                O[i][1][hh*2]   *= cr;  O[i][1][hh*2+1] *= cr;
            }
        __syncthreads();   // everyone done reading red maxes + P stores visible
        if (c == 0) {
#pragma unroll
            for (int i = 0; i < 4; i++)
#pragma unroll
                for (int hh = 0; hh < 2; hh++)
                    red[(wm*64 + i*16 + hh*8 + g)*4 + wn] = rs[i][hh];
        }
        __syncthreads();
#pragma unroll
        for (int i = 0; i < 4; i++)
#pragma unroll
            for (int hh = 0; hh < 2; hh++) {
                int row = wm*64 + i*16 + hh*8 + g;
                float sum = red[row*4+0] + red[row*4+1] + red[row*4+2] + red[row*4+3];
                l[i][hh] = l[i][hh]*corr[i][hh] + sum;
            }

        // ---- O += P V (tf32 mma), warp tile 64q x 16d ----
#pragma unroll
        for (int ks = 0; ks < 16; ks++) {
            const int k0 = ks * 8;
            unsigned a[4][4];
#pragma unroll
            for (int i = 0; i < 4; i++) {
                int row = wm*64 + i*16 + g;
                a[i][0] = Ps[row*PP + k0 + c];
                a[i][1] = Ps[(row+8)*PP + k0 + c];
                a[i][2] = Ps[row*PP + k0 + 4 + c];
                a[i][3] = Ps[(row+8)*PP + k0 + 4 + c];
            }
#pragma unroll
            for (int j = 0; j < 2; j++) {
                int n0 = wn*16 + j*8;
                unsigned b0 = Vs[(k0 + c)*VP + n0 + g];
                unsigned b1 = Vs[(k0 + 4 + c)*VP + n0 + g];
#pragma unroll
                for (int i = 0; i < 4; i++)
                    mma_tf32(O[i][j], a[i][0], a[i][1], a[i][2], a[i][3], b0, b1);
            }
        }
        __syncthreads();
    }

    // ---- epilogue: 1/l, q_mask, write [B, SP, NH*HD] ----
#pragma unroll
    for (int i = 0; i < 4; i++)
#pragma unroll
        for (int hh = 0; hh < 2; hh++) {
            int row = wm*64 + i*16 + hh*8 + g;
            int qg = qt*128 + row;
            float inv = (2*qg < len) ? (1.0f / l[i][hh]) : 0.0f;
#pragma unroll
            for (int j = 0; j < 2; j++) {
                int col = wn*16 + j*8 + 2*c;
                float2 o = make_float2(O[i][j][hh*2]*inv, O[i][j][hh*2+1]*inv);
                *(float2*)&out[((size_t)(b*SP_ + qg))*(NH_*HD_) + h*HD_ + col] = o;
            }
        }
}

// ---------------- launcher ----------------------------------------------------
extern "C" void kernel_launch(void* const* d_in, const int* in_sizes, int n_in,
                              void* d_out, int out_size) {
    const float* hidden = (const float*)d_in[0];
    const void*  mask   = d_in[1];
    const float* W      = (const float*)d_in[2];
    const float* bias   = (const float*)d_in[3];
    float* out = (float*)d_out;

    len_kernel<<<1, 256>>>(mask);

    dim3 gg(NQKV_/128, (B_*S_)/128);
    qkv_gemm_tc<<<gg, 256>>>(hidden, W, bias);

    rope_k_kernel<<<(B_*NH_*S_*32)/256, 256>>>();
    pool_rope_q_kernel<<<(B_*NH_*SP_*32)/256, 256>>>();

    const int attn_smem = (128*QP + 128*QP + 128*VP + 128*PP) * 4 + 128*4*4;
    cudaFuncSetAttribute(attn_tc, cudaFuncAttributeMaxDynamicSharedMemorySize, attn_smem);
    dim3 ga(SP_/128, NH_, B_);
    attn_tc<<<ga, 256, attn_smem>>>(out);
}